// round 10
// baseline (speedup 1.0000x reference)
#include <cuda_runtime.h>
#include <cfloat>

#define BB   8
#define NN   8192
#define DD   64
#define SS   1024
#define KNB  16          // NSAMPLE
#define WNC  16          // weightnet out channels
#define OUTC 128
#define CINC 67          // 3 + D
#define AGGW (CINC*WNC)  // 1072

#define OFF_OUT (BB*3*SS)                 // 24576
#define OFF_IDX (BB*3*SS + BB*OUTC*SS)    // 1073152

// ---------------- scratch: ONE static device buffer, no allocation ----------------
#define SC_XYZT   0
#define SC_PTST   (SC_XYZT + BB*NN*4)
#define SC_NEWXYZ (SC_PTST + BB*NN*DD)
#define SC_KNN    (SC_NEWXYZ + BB*SS*3)
#define SC_PERM   (SC_KNN + BB*SS*KNB)
#define SC_AGG    (SC_PERM + BB*NN)
#define SC_TOTAL  (SC_AGG + (size_t)BB*SS*AGGW)

__device__ __align__(16) float g_scratch[SC_TOTAL];

#define g_xyzT4  ((float4*)(g_scratch + SC_XYZT))
#define g_ptsT   (g_scratch + SC_PTST)
#define g_newxyz (g_scratch + SC_NEWXYZ)
#define g_knn    ((int*)(g_scratch + SC_KNN))
#define g_perm   ((int*)(g_scratch + SC_PERM))
#define g_agg    (g_scratch + SC_AGG)

// ---------------- packed f32x2 helpers (Blackwell, exact per-element rn) ----------------
__device__ __forceinline__ unsigned long long pk2(float lo, float hi) {
    unsigned long long r;
    asm("mov.b64 %0, {%1, %2};" : "=l"(r) : "f"(lo), "f"(hi));
    return r;
}
__device__ __forceinline__ void upk2(unsigned long long v, float& lo, float& hi) {
    asm("mov.b64 {%0, %1}, %2;" : "=f"(lo), "=f"(hi) : "l"(v));
}
__device__ __forceinline__ unsigned long long addx2(unsigned long long a, unsigned long long b) {
    unsigned long long r;
    asm("add.rn.f32x2 %0, %1, %2;" : "=l"(r) : "l"(a), "l"(b));
    return r;
}
__device__ __forceinline__ unsigned long long mulx2(unsigned long long a, unsigned long long b) {
    unsigned long long r;
    asm("mul.rn.f32x2 %0, %1, %2;" : "=l"(r) : "l"(a), "l"(b));
    return r;
}

// ---------------- layout transforms ----------------
__global__ void xyzT_kernel(const float* __restrict__ xyz) {
    int i = blockIdx.x * 256 + threadIdx.x;     // 0 .. BB*NN-1
    int b = i >> 13, n = i & (NN - 1);
    const float* X = xyz + (size_t)b * 3 * NN;
    g_xyzT4[i] = make_float4(X[n], X[NN + n], X[2 * NN + n], 0.f);
}

__global__ void ptsT_kernel(const float* __restrict__ pts) {
    __shared__ float tile[32][33];
    int b = blockIdx.z;
    int n0 = blockIdx.x * 32, d0 = blockIdx.y * 32;
    int tx = threadIdx.x, ty = threadIdx.y;
    #pragma unroll
    for (int i = 0; i < 32; i += 8)
        tile[ty + i][tx] = pts[(size_t)b * DD * NN + (size_t)(d0 + ty + i) * NN + n0 + tx];
    __syncthreads();
    #pragma unroll
    for (int i = 0; i < 32; i += 8)
        g_ptsT[((size_t)b * NN + n0 + ty + i) * DD + d0 + tx] = tile[tx][ty + i];
}

// 4-bit expand for Morton (bits -> positions 0,3,6,9)
__device__ __forceinline__ unsigned expand4(unsigned v) {
    return (v & 1u) | ((v & 2u) << 2) | ((v & 4u) << 4) | ((v & 8u) << 6);
}

// ---------------- FPS: 1 block per batch, 1024 threads, 8 pts/thread ----------------
// Morton-binned point assignment (permutation staged via global scratch; no dynamic
// smem) + exact-conservative two-level sphere pruning. Update path keeps strict rn
// fp32 (packed f32x2); gates carry a 5e-4 margin, so results match the unpruned version.
__global__ void __launch_bounds__(1024, 1) fps_kernel(float* __restrict__ dout) {
    __shared__ unsigned s_cnt[4096];        // 16KB bucket counts -> offsets
    __shared__ float    s_bd[2][32];
    __shared__ unsigned s_bi[2][32];
    __shared__ float    s_rmin[3][32], s_rmax[3][32];
    __shared__ unsigned s_wsum[32];
    __shared__ float    s_box[6];

    int b = blockIdx.x;
    int t = threadIdx.x;
    int lane = t & 31, warp = t >> 5;
    int* perm = g_perm + b * NN;

    // ---- phase 1: load (strided), bbox reduce ----
    float lx[8], ly[8], lz[8];
    float mnx = FLT_MAX, mny = FLT_MAX, mnz = FLT_MAX;
    float mxx = -FLT_MAX, mxy = -FLT_MAX, mxz = -FLT_MAX;
    #pragma unroll
    for (int j = 0; j < 8; j++) {
        float4 p = g_xyzT4[b * NN + t + (j << 10)];
        lx[j] = p.x; ly[j] = p.y; lz[j] = p.z;
        mnx = fminf(mnx, p.x); mxx = fmaxf(mxx, p.x);
        mny = fminf(mny, p.y); mxy = fmaxf(mxy, p.y);
        mnz = fminf(mnz, p.z); mxz = fmaxf(mxz, p.z);
    }
    #pragma unroll
    for (int off = 16; off; off >>= 1) {
        mnx = fminf(mnx, __shfl_xor_sync(0xffffffffu, mnx, off));
        mny = fminf(mny, __shfl_xor_sync(0xffffffffu, mny, off));
        mnz = fminf(mnz, __shfl_xor_sync(0xffffffffu, mnz, off));
        mxx = fmaxf(mxx, __shfl_xor_sync(0xffffffffu, mxx, off));
        mxy = fmaxf(mxy, __shfl_xor_sync(0xffffffffu, mxy, off));
        mxz = fmaxf(mxz, __shfl_xor_sync(0xffffffffu, mxz, off));
    }
    if (lane == 0) {
        s_rmin[0][warp] = mnx; s_rmin[1][warp] = mny; s_rmin[2][warp] = mnz;
        s_rmax[0][warp] = mxx; s_rmax[1][warp] = mxy; s_rmax[2][warp] = mxz;
    }
    // zero counts while waiting
    #pragma unroll
    for (int j = 0; j < 4; j++) s_cnt[t + (j << 10)] = 0u;
    __syncthreads();
    if (warp == 0) {
        float a0 = s_rmin[0][lane], a1 = s_rmin[1][lane], a2 = s_rmin[2][lane];
        float b0 = s_rmax[0][lane], b1 = s_rmax[1][lane], b2 = s_rmax[2][lane];
        #pragma unroll
        for (int off = 16; off; off >>= 1) {
            a0 = fminf(a0, __shfl_xor_sync(0xffffffffu, a0, off));
            a1 = fminf(a1, __shfl_xor_sync(0xffffffffu, a1, off));
            a2 = fminf(a2, __shfl_xor_sync(0xffffffffu, a2, off));
            b0 = fmaxf(b0, __shfl_xor_sync(0xffffffffu, b0, off));
            b1 = fmaxf(b1, __shfl_xor_sync(0xffffffffu, b1, off));
            b2 = fmaxf(b2, __shfl_xor_sync(0xffffffffu, b2, off));
        }
        if (lane == 0) {
            s_box[0] = a0; s_box[1] = a1; s_box[2] = a2;
            s_box[3] = b0; s_box[4] = b1; s_box[5] = b2;
        }
    }
    __syncthreads();

    // ---- phase 2: Morton codes + histogram ----
    float bx = s_box[0], by = s_box[1], bz = s_box[2];
    float sx = 15.999f / fmaxf(s_box[3] - bx, 1e-12f);
    float sy = 15.999f / fmaxf(s_box[4] - by, 1e-12f);
    float sz = 15.999f / fmaxf(s_box[5] - bz, 1e-12f);
    unsigned code8[8];
    #pragma unroll
    for (int j = 0; j < 8; j++) {
        unsigned gx = (unsigned)((lx[j] - bx) * sx);
        unsigned gy = (unsigned)((ly[j] - by) * sy);
        unsigned gz = (unsigned)((lz[j] - bz) * sz);
        gx = min(gx, 15u); gy = min(gy, 15u); gz = min(gz, 15u);
        code8[j] = expand4(gx) | (expand4(gy) << 1) | (expand4(gz) << 2);
        atomicAdd(&s_cnt[code8[j]], 1u);
    }
    __syncthreads();

    // ---- phase 3: exclusive scan of 4096 counts (4 per thread) ----
    {
        unsigned a0 = s_cnt[4 * t], a1 = s_cnt[4 * t + 1],
                 a2 = s_cnt[4 * t + 2], a3 = s_cnt[4 * t + 3];
        unsigned ts = a0 + a1 + a2 + a3;
        unsigned inc = ts;
        #pragma unroll
        for (int off = 1; off < 32; off <<= 1) {
            unsigned n = __shfl_up_sync(0xffffffffu, inc, off);
            if (lane >= off) inc += n;
        }
        if (lane == 31) s_wsum[warp] = inc;
        __syncthreads();
        if (warp == 0) {
            unsigned wv = s_wsum[lane];
            unsigned wi = wv;
            #pragma unroll
            for (int off = 1; off < 32; off <<= 1) {
                unsigned n = __shfl_up_sync(0xffffffffu, wi, off);
                if (lane >= off) wi += n;
            }
            s_wsum[lane] = wi - wv;   // exclusive warp offsets
        }
        __syncthreads();
        unsigned exc = s_wsum[warp] + inc - ts;
        s_cnt[4 * t]     = exc;
        s_cnt[4 * t + 1] = exc + a0;
        s_cnt[4 * t + 2] = exc + a0 + a1;
        s_cnt[4 * t + 3] = exc + a0 + a1 + a2;
    }
    __syncthreads();

    // ---- phase 4: scatter permutation to global scratch ----
    #pragma unroll
    for (int j = 0; j < 8; j++) {
        unsigned pos = atomicAdd(&s_cnt[code8[j]], 1u);
        perm[pos] = t + (j << 10);
    }
    __syncthreads();   // block-wide visibility of perm[] (global, same block)

    // ---- phase 5: reload 8 consecutive Morton-sorted points; build spheres ----
    int oi[8];
    unsigned long long ppx[4], ppy[4], ppz[4];
    float dist[8];
    float tmnx = FLT_MAX, tmny = FLT_MAX, tmnz = FLT_MAX;
    float tmxx = -FLT_MAX, tmxy = -FLT_MAX, tmxz = -FLT_MAX;
    {
        float qx[8], qy[8], qz[8];
        #pragma unroll
        for (int j = 0; j < 8; j++) {
            oi[j] = perm[t * 8 + j];
            float4 p = g_xyzT4[b * NN + oi[j]];
            qx[j] = p.x; qy[j] = p.y; qz[j] = p.z;
            tmnx = fminf(tmnx, p.x); tmxx = fmaxf(tmxx, p.x);
            tmny = fminf(tmny, p.y); tmxy = fmaxf(tmxy, p.y);
            tmnz = fminf(tmnz, p.z); tmxz = fmaxf(tmxz, p.z);
            dist[j] = 1e10f;
        }
        #pragma unroll
        for (int j = 0; j < 4; j++) {
            ppx[j] = pk2(qx[2 * j], qx[2 * j + 1]);
            ppy[j] = pk2(qy[2 * j], qy[2 * j + 1]);
            ppz[j] = pk2(qz[2 * j], qz[2 * j + 1]);
        }
    }
    float tcx = 0.5f * (tmnx + tmxx), tcy = 0.5f * (tmny + tmxy), tcz = 0.5f * (tmnz + tmxz);
    float tex = 0.5f * (tmxx - tmnx), tey = 0.5f * (tmxy - tmny), tez = 0.5f * (tmxz - tmnz);
    float r_t = __fsqrt_rn(tex * tex + tey * tey + tez * tez) * 1.0005f + 1e-7f;
    // warp box
    float wmnx = tmnx, wmny = tmny, wmnz = tmnz, wmxx = tmxx, wmxy = tmxy, wmxz = tmxz;
    #pragma unroll
    for (int off = 16; off; off >>= 1) {
        wmnx = fminf(wmnx, __shfl_xor_sync(0xffffffffu, wmnx, off));
        wmny = fminf(wmny, __shfl_xor_sync(0xffffffffu, wmny, off));
        wmnz = fminf(wmnz, __shfl_xor_sync(0xffffffffu, wmnz, off));
        wmxx = fmaxf(wmxx, __shfl_xor_sync(0xffffffffu, wmxx, off));
        wmxy = fmaxf(wmxy, __shfl_xor_sync(0xffffffffu, wmxy, off));
        wmxz = fmaxf(wmxz, __shfl_xor_sync(0xffffffffu, wmxz, off));
    }
    float wcx = 0.5f * (wmnx + wmxx), wcy = 0.5f * (wmny + wmxy), wcz = 0.5f * (wmnz + wmxz);
    float wex = 0.5f * (wmxx - wmnx), wey = 0.5f * (wmxy - wmny), wez = 0.5f * (wmxz - wmnz);
    float r_w = __fsqrt_rn(wex * wex + wey * wey + wez * wez) * 1.0005f + 1e-7f;

    float m_t = 1e10f;       unsigned bi_t = 0x7fffffffu;  float thr_t = 1e30f;
    float wmax = 1e10f;      unsigned wbi  = 0x7fffffffu;  float thr_w = 1e30f;

    __syncthreads();

    // ---- main loop ----
    int far = 0;
    for (int s = 0; s < SS; s++) {
        float4 c = g_xyzT4[b * NN + far];   // broadcast (L1)
        if (t == 0) {
            dout[b * 3 * SS + s]          = c.x;
            dout[b * 3 * SS + SS + s]     = c.y;
            dout[b * 3 * SS + 2 * SS + s] = c.z;
            dout[OFF_IDX + b * SS + s]    = (float)far;
            int gs = (b * SS + s) * 3;
            g_newxyz[gs] = c.x; g_newxyz[gs + 1] = c.y; g_newxyz[gs + 2] = c.z;
        }
        // warp-level gate (uniform): skip iff |c - wc|^2 >= (sqrt(wmax)*marg + r_w)^2
        float dwx = c.x - wcx, dwy = c.y - wcy, dwz = c.z - wcz;
        float d2w = dwx * dwx + dwy * dwy + dwz * dwz;
        if (d2w < thr_w) {
            // thread-level gate (divergent)
            float dtx = c.x - tcx, dty = c.y - tcy, dtz = c.z - tcz;
            float d2t = dtx * dtx + dty * dty + dtz * dtz;
            if (d2t < thr_t) {
                unsigned long long ncx = pk2(-c.x, -c.x);
                unsigned long long ncy = pk2(-c.y, -c.y);
                unsigned long long ncz = pk2(-c.z, -c.z);
                #pragma unroll
                for (int j = 0; j < 4; j++) {
                    unsigned long long dx = addx2(ppx[j], ncx);
                    unsigned long long dy = addx2(ppy[j], ncy);
                    unsigned long long dz = addx2(ppz[j], ncz);
                    unsigned long long xx = mulx2(dx, dx);
                    unsigned long long yy = mulx2(dy, dy);
                    unsigned long long s1 = addx2(xx, yy);
                    unsigned long long zz = mulx2(dz, dz);
                    unsigned long long dd = addx2(s1, zz);
                    float d0, d1;
                    upk2(dd, d0, d1);
                    dist[2 * j]     = fminf(dist[2 * j], d0);
                    dist[2 * j + 1] = fminf(dist[2 * j + 1], d1);
                }
                // recompute thread max with (dist desc, orig idx asc) tie rule
                float m = dist[0]; unsigned bi = (unsigned)oi[0];
                #pragma unroll
                for (int e = 1; e < 8; e++) {
                    bool better = (dist[e] > m) || (dist[e] == m && (unsigned)oi[e] < bi);
                    if (better) { m = dist[e]; bi = (unsigned)oi[e]; }
                }
                m_t = m; bi_t = bi;
                float st = __fsqrt_rn(m_t) * 1.0005f + r_t;
                thr_t = st * st;
            }
            // warp redux (all lanes of this warp are here; gate was uniform)
            unsigned mb   = __float_as_uint(m_t);
            unsigned wmb  = __reduce_max_sync(0xffffffffu, mb);
            unsigned cand = (mb == wmb) ? bi_t : 0xffffffffu;
            wbi  = __reduce_min_sync(0xffffffffu, cand);
            wmax = __uint_as_float(wmb);
            float sw = __fsqrt_rn(wmax) * 1.0005f + r_w;
            thr_w = sw * sw;
        }
        if (lane == 0) { s_bd[s & 1][warp] = wmax; s_bi[s & 1][warp] = wbi; }
        __syncthreads();
        unsigned vb = __float_as_uint(s_bd[s & 1][lane]);
        unsigned vi = s_bi[s & 1][lane];
        unsigned gmax = __reduce_max_sync(0xffffffffu, vb);
        unsigned gc   = (vb == gmax) ? vi : 0xffffffffu;
        far = (int)__reduce_min_sync(0xffffffffu, gc);
    }
}

// ---------------- KNN: 1 warp per sampled point, warp-collective exact top-16 ----------------
__global__ void __launch_bounds__(512) knn_kernel() {
    int w = threadIdx.x >> 5, lane = threadIdx.x & 31;
    int gid = blockIdx.x * 16 + w;          // 0..8191
    int b = gid >> 10;

    float qx = g_newxyz[gid * 3], qy = g_newxyz[gid * 3 + 1], qz = g_newxyz[gid * 3 + 2];
    const float4* X4 = g_xyzT4 + b * NN;

    float st_d = FLT_MAX;            // stored entry (meaningful in lanes 0..15)
    int   st_i = 0x7FFFFFFF;
    float worst_d = FLT_MAX;         // warp-uniform: max dist among stored, tie max idx
    int   worst_i = 0x7FFFFFFF;

    for (int i = lane; i < NN; i += 32) {
        float4 p = X4[i];
        float dx = __fsub_rn(qx, p.x);
        float dy = __fsub_rn(qy, p.y);
        float dz = __fsub_rn(qz, p.z);
        float d  = __fadd_rn(__fadd_rn(__fmul_rn(dx, dx), __fmul_rn(dy, dy)),
                             __fmul_rn(dz, dz));
        bool pass = (d < worst_d) || (d == worst_d && i < worst_i);
        unsigned mask = __ballot_sync(0xffffffffu, pass);
        while (mask) {                       // warp-uniform loop
            int src = __ffs(mask) - 1; mask &= mask - 1;
            float dc = __shfl_sync(0xffffffffu, d, src);
            int   ic = __shfl_sync(0xffffffffu, i, src);
            if (dc < worst_d || (dc == worst_d && ic < worst_i)) {   // uniform re-check
                bool meq = (lane < 16) && (st_d == worst_d) && (st_i == worst_i);
                unsigned bl = __ballot_sync(0xffffffffu, meq);
                int wl = __ffs(bl) - 1;
                if (lane == wl) { st_d = dc; st_i = ic; }
                unsigned db = (lane < 16) ? __float_as_uint(st_d) : 0u;
                unsigned wd = __reduce_max_sync(0xffffffffu, db);
                unsigned ci = (db == wd && lane < 16) ? (unsigned)st_i : 0u;
                unsigned wi = __reduce_max_sync(0xffffffffu, ci);
                worst_d = __uint_as_float(wd);
                worst_i = (int)wi;
            }
        }
    }
    bool act = (lane < 16);
    #pragma unroll 1
    for (int r = 0; r < 16; r++) {
        unsigned db = act ? __float_as_uint(st_d) : 0xFFFFFFFFu;
        unsigned md = __reduce_min_sync(0xffffffffu, db);
        unsigned ib = (act && db == md) ? (unsigned)st_i : 0xFFFFFFFFu;
        unsigned mi = __reduce_min_sync(0xffffffffu, ib);
        if (act && db == md && (unsigned)st_i == mi) {
            g_knn[gid * 16 + r] = st_i;
            act = false;
        }
    }
}

// ---------------- gather + WeightNet MLP + einsum agg: 1 block per point ----------------
__global__ void __launch_bounds__(128) agg_kernel(
    const float* __restrict__ w1, const float* __restrict__ b1,
    const float* __restrict__ w2, const float* __restrict__ b2,
    const float* __restrict__ w3, const float* __restrict__ b3)
{
    __shared__ float feat[KNB][CINC + 1];   // pad to 68
    __shared__ float wts[KNB][WNC];
    __shared__ int   nn[KNB];
    __shared__ float q[3];

    int t = threadIdx.x;
    int pid = blockIdx.x;
    int b = pid >> 10;

    if (t < KNB) nn[t] = g_knn[pid * KNB + t];
    if (t < 3)   q[t]  = g_newxyz[pid * 3 + t];
    __syncthreads();

    if (t < KNB) {
        float4 pp = g_xyzT4[b * NN + nn[t]];
        float gx = pp.x - q[0], gy = pp.y - q[1], gz = pp.z - q[2];
        feat[t][0] = gx; feat[t][1] = gy; feat[t][2] = gz;
        float h1[8], h2[8];
        #pragma unroll
        for (int j = 0; j < 8; j++) {
            float a = b1[j];
            a = fmaf(gx, w1[j], a);
            a = fmaf(gy, w1[8 + j], a);
            a = fmaf(gz, w1[16 + j], a);
            h1[j] = fmaxf(a, 0.f);
        }
        #pragma unroll
        for (int j = 0; j < 8; j++) {
            float a = b2[j];
            #pragma unroll
            for (int i = 0; i < 8; i++) a = fmaf(h1[i], w2[i * 8 + j], a);
            h2[j] = fmaxf(a, 0.f);
        }
        #pragma unroll
        for (int j = 0; j < 16; j++) {
            float a = b3[j];
            #pragma unroll
            for (int i = 0; i < 8; i++) a = fmaf(h2[i], w3[i * 16 + j], a);
            wts[t][j] = fmaxf(a, 0.f);
        }
    }
    for (int idx = t; idx < KNB * DD; idx += 128) {
        int k = idx >> 6, d = idx & 63;
        feat[k][3 + d] = g_ptsT[((size_t)b * NN + nn[k]) * DD + d];
    }
    __syncthreads();

    for (int j = t; j < AGGW; j += 128) {
        int c = j >> 4, w = j & 15;
        float a = 0.f;
        #pragma unroll
        for (int k = 0; k < KNB; k++) a = fmaf(feat[k][c], wts[k][w], a);
        g_agg[(size_t)pid * AGGW + j] = a;
    }
}

// ---------------- final linear: GEMM [8192 x 1072] * [1072 x 128] + bias + leaky ----------------
__global__ void __launch_bounds__(256) gemm_kernel(
    const float* __restrict__ lin_w, const float* __restrict__ lin_b,
    float* __restrict__ dout)
{
    __shared__ float As[64][16];
    __shared__ float Bs[16][128];
    int t = threadIdx.x;
    int row0 = blockIdx.x * 64;
    int cg = t & 31, rg = t >> 5;

    float acc[8][4];
    #pragma unroll
    for (int i = 0; i < 8; i++)
        #pragma unroll
        for (int j = 0; j < 4; j++) acc[i][j] = 0.f;

    for (int k0 = 0; k0 < AGGW; k0 += 16) {
        __syncthreads();
        {
            int r = t >> 2, kk = (t & 3) << 2;
            float4 v = *(const float4*)&g_agg[(size_t)(row0 + r) * AGGW + k0 + kk];
            *(float4*)&As[r][kk] = v;
        }
        {
            int kk = t >> 5, c = (t & 31) << 2;
            *(float4*)&Bs[kk][c]     = *(const float4*)&lin_w[(size_t)(k0 + kk) * 128 + c];
            *(float4*)&Bs[kk + 8][c] = *(const float4*)&lin_w[(size_t)(k0 + kk + 8) * 128 + c];
        }
        __syncthreads();
        #pragma unroll
        for (int kk = 0; kk < 16; kk++) {
            float4 bv = *(float4*)&Bs[kk][cg << 2];
            #pragma unroll
            for (int ri = 0; ri < 8; ri++) {
                float av = As[rg * 8 + ri][kk];
                acc[ri][0] = fmaf(av, bv.x, acc[ri][0]);
                acc[ri][1] = fmaf(av, bv.y, acc[ri][1]);
                acc[ri][2] = fmaf(av, bv.z, acc[ri][2]);
                acc[ri][3] = fmaf(av, bv.w, acc[ri][3]);
            }
        }
    }
    float bias[4];
    #pragma unroll
    for (int ci = 0; ci < 4; ci++) bias[ci] = lin_b[(cg << 2) + ci];
    #pragma unroll
    for (int ri = 0; ri < 8; ri++) {
        int p = row0 + rg * 8 + ri;
        int b = p >> 10, s = p & 1023;
        #pragma unroll
        for (int ci = 0; ci < 4; ci++) {
            int c = (cg << 2) + ci;
            float v = acc[ri][ci] + bias[ci];
            v = (v > 0.f) ? v : 0.1f * v;
            dout[OFF_OUT + ((size_t)b * OUTC + c) * SS + s] = v;
        }
    }
}

// ---------------- launch ----------------
extern "C" void kernel_launch(void* const* d_in, const int* in_sizes, int n_in,
                              void* d_out, int out_size) {
    const float* xyz = (const float*)d_in[0];
    const float* pts = (const float*)d_in[1];
    const float* w1  = (const float*)d_in[2];
    const float* b1  = (const float*)d_in[3];
    const float* w2  = (const float*)d_in[4];
    const float* b2  = (const float*)d_in[5];
    const float* w3  = (const float*)d_in[6];
    const float* b3  = (const float*)d_in[7];
    const float* lw  = (const float*)d_in[8];
    const float* lb  = (const float*)d_in[9];
    float* out = (float*)d_out;

    xyzT_kernel<<<BB * NN / 256, 256>>>(xyz);
    ptsT_kernel<<<dim3(NN / 32, DD / 32, BB), dim3(32, 8)>>>(pts);
    fps_kernel<<<BB, 1024>>>(out);
    knn_kernel<<<BB * SS / 16, 512>>>();
    agg_kernel<<<BB * SS, 128>>>(w1, b1, w2, b2, w3, b3);
    gemm_kernel<<<BB * SS / 64, 256>>>(lw, lb, out);
}

// round 14
// speedup vs baseline: 1.2829x; 1.2829x over previous
#include <cuda_runtime.h>
#include <cfloat>

#define BB   8
#define NN   8192
#define DD   64
#define SS   1024
#define KNB  16          // NSAMPLE
#define WNC  16          // weightnet out channels
#define OUTC 128
#define CINC 67          // 3 + D
#define AGGW (CINC*WNC)  // 1072

#define OFF_OUT (BB*3*SS)                 // 24576
#define OFF_IDX (BB*3*SS + BB*OUTC*SS)    // 1073152

// ---------------- scratch: ONE static device buffer, no allocation ----------------
#define SC_XYZT   0
#define SC_PTST   (SC_XYZT + BB*NN*4)
#define SC_NEWXYZ (SC_PTST + BB*NN*DD)
#define SC_KNN    (SC_NEWXYZ + BB*SS*3)
#define SC_AGG    (SC_KNN + BB*SS*KNB)
#define SC_TOTAL  (SC_AGG + (size_t)BB*SS*AGGW)

__device__ __align__(16) float g_scratch[SC_TOTAL];

#define g_xyzT4  ((float4*)(g_scratch + SC_XYZT))
#define g_ptsT   (g_scratch + SC_PTST)
#define g_newxyz (g_scratch + SC_NEWXYZ)
#define g_knn    ((int*)(g_scratch + SC_KNN))
#define g_agg    (g_scratch + SC_AGG)

// ---------------- packed f32x2 helpers (Blackwell, exact per-element rn) ----------------
__device__ __forceinline__ unsigned long long pk2(float lo, float hi) {
    unsigned long long r;
    asm("mov.b64 %0, {%1, %2};" : "=l"(r) : "f"(lo), "f"(hi));
    return r;
}
__device__ __forceinline__ void upk2(unsigned long long v, float& lo, float& hi) {
    asm("mov.b64 {%0, %1}, %2;" : "=f"(lo), "=f"(hi) : "l"(v));
}
__device__ __forceinline__ unsigned long long addx2(unsigned long long a, unsigned long long b) {
    unsigned long long r;
    asm("add.rn.f32x2 %0, %1, %2;" : "=l"(r) : "l"(a), "l"(b));
    return r;
}
__device__ __forceinline__ unsigned long long mulx2(unsigned long long a, unsigned long long b) {
    unsigned long long r;
    asm("mul.rn.f32x2 %0, %1, %2;" : "=l"(r) : "l"(a), "l"(b));
    return r;
}

// ---------------- layout transforms ----------------
__global__ void xyzT_kernel(const float* __restrict__ xyz) {
    int i = blockIdx.x * 256 + threadIdx.x;     // 0 .. BB*NN-1
    int b = i >> 13, n = i & (NN - 1);
    const float* X = xyz + (size_t)b * 3 * NN;
    g_xyzT4[i] = make_float4(X[n], X[NN + n], X[2 * NN + n], 0.f);
}

__global__ void ptsT_kernel(const float* __restrict__ pts) {
    __shared__ float tile[32][33];
    int b = blockIdx.z;
    int n0 = blockIdx.x * 32, d0 = blockIdx.y * 32;
    int tx = threadIdx.x, ty = threadIdx.y;
    #pragma unroll
    for (int i = 0; i < 32; i += 8)
        tile[ty + i][tx] = pts[(size_t)b * DD * NN + (size_t)(d0 + ty + i) * NN + n0 + tx];
    __syncthreads();
    #pragma unroll
    for (int i = 0; i < 32; i += 8)
        g_ptsT[((size_t)b * NN + n0 + ty + i) * DD + d0 + tx] = tile[tx][ty + i];
}

// ---------------- FPS: 1 block per batch, 1024 threads, 8 pts/thread ----------------
// Hot loop: packed f32x2 dist (exact rn), FMNMX min-update + index-free max tree.
// Argmax index resolved once per warp on matching lanes only (exact tie rule:
// smallest original index among points achieving the max).
__global__ void __launch_bounds__(1024, 1) fps_kernel(float* __restrict__ dout) {
    int b = blockIdx.x;
    int t = threadIdx.x;
    int lane = t & 31, warp = t >> 5;

    // element e (0..7) is point t + (e<<10); pairs (2j, 2j+1) packed
    unsigned long long ppx[4], ppy[4], ppz[4];
    float dist[8];
    #pragma unroll
    for (int j = 0; j < 4; j++) {
        float4 p0 = g_xyzT4[b * NN + t + ((2 * j) << 10)];
        float4 p1 = g_xyzT4[b * NN + t + ((2 * j + 1) << 10)];
        ppx[j] = pk2(p0.x, p1.x);
        ppy[j] = pk2(p0.y, p1.y);
        ppz[j] = pk2(p0.z, p1.z);
        dist[2 * j] = 1e10f; dist[2 * j + 1] = 1e10f;
    }

    __shared__ float    s_bd[2][32];
    __shared__ unsigned s_bi[2][32];

    int far = 0;
    for (int s = 0; s < SS; s++) {
        float4 c = g_xyzT4[b * NN + far];   // broadcast load (L1-resident)
        if (t == 0) {
            dout[b * 3 * SS + s]          = c.x;
            dout[b * 3 * SS + SS + s]     = c.y;
            dout[b * 3 * SS + 2 * SS + s] = c.z;
            dout[OFF_IDX + b * SS + s]    = (float)far;
            int gs = (b * SS + s) * 3;
            g_newxyz[gs] = c.x; g_newxyz[gs + 1] = c.y; g_newxyz[gs + 2] = c.z;
        }
        // negated centroid, packed (exact: rn-add of -c == rn-sub of c)
        unsigned long long ncx = pk2(-c.x, -c.x);
        unsigned long long ncy = pk2(-c.y, -c.y);
        unsigned long long ncz = pk2(-c.z, -c.z);

        #pragma unroll
        for (int j = 0; j < 4; j++) {
            unsigned long long dx = addx2(ppx[j], ncx);
            unsigned long long dy = addx2(ppy[j], ncy);
            unsigned long long dz = addx2(ppz[j], ncz);
            unsigned long long xx = mulx2(dx, dx);
            unsigned long long yy = mulx2(dy, dy);
            unsigned long long s1 = addx2(xx, yy);
            unsigned long long zz = mulx2(dz, dz);
            unsigned long long dd = addx2(s1, zz);
            float d0, d1;
            upk2(dd, d0, d1);
            dist[2 * j]     = fminf(dist[2 * j], d0);
            dist[2 * j + 1] = fminf(dist[2 * j + 1], d1);
        }
        // index-free per-thread max (FMNMX tree)
        float m01 = fmaxf(dist[0], dist[1]);
        float m23 = fmaxf(dist[2], dist[3]);
        float m45 = fmaxf(dist[4], dist[5]);
        float m67 = fmaxf(dist[6], dist[7]);
        float m = fmaxf(fmaxf(m01, m23), fmaxf(m45, m67));

        // warp max via REDUX (dist >= 0: float bits order as u32)
        unsigned mb  = __float_as_uint(m);
        unsigned wmb = __reduce_max_sync(0xffffffffu, mb);
        // index resolution only on matching lanes; ascending e => ascending idx,
        // min over matches == first occurrence (exact argmax tie rule)
        unsigned cand = 0xffffffffu;
        if (mb == wmb) {
            #pragma unroll
            for (int e = 7; e >= 0; e--)
                if (dist[e] == m) cand = (unsigned)(t + (e << 10));
        }
        unsigned wbi = __reduce_min_sync(0xffffffffu, cand);
        if (lane == 0) { s_bd[s & 1][warp] = __uint_as_float(wmb); s_bi[s & 1][warp] = wbi; }
        __syncthreads();
        // level-2: every warp reduces the 32 per-warp results (single barrier/iter)
        unsigned vb = __float_as_uint(s_bd[s & 1][lane]);
        unsigned vi = s_bi[s & 1][lane];
        unsigned gmax = __reduce_max_sync(0xffffffffu, vb);
        unsigned gc   = (vb == gmax) ? vi : 0xffffffffu;
        far = (int)__reduce_min_sync(0xffffffffu, gc);
    }
}

// ---------------- KNN: 1 warp per sampled point, warp-collective exact top-16 ----------------
// 4 candidates per lane-iteration (MLP 4). Top-16 set is order-invariant under the
// lexicographic (dist, idx) accept/evict rules, so batch processing order is safe.
// Gate d <= worst_d only over-triggers; the uniform re-check inside is exact.
__global__ void __launch_bounds__(512) knn_kernel() {
    int w = threadIdx.x >> 5, lane = threadIdx.x & 31;
    int gid = blockIdx.x * 16 + w;          // 0..8191
    int b = gid >> 10;

    float qx = g_newxyz[gid * 3], qy = g_newxyz[gid * 3 + 1], qz = g_newxyz[gid * 3 + 2];
    const float4* X4 = g_xyzT4 + b * NN;

    float st_d = FLT_MAX;            // stored entry (meaningful in lanes 0..15)
    int   st_i = 0x7FFFFFFF;
    float worst_d = FLT_MAX;         // warp-uniform: max dist among stored, tie max idx
    int   worst_i = 0x7FFFFFFF;

    for (int i = lane; i < NN; i += 128) {
        float4 p[4];
        #pragma unroll
        for (int u = 0; u < 4; u++) p[u] = X4[i + u * 32];
        float d[4];
        #pragma unroll
        for (int u = 0; u < 4; u++) {
            float dx = __fsub_rn(qx, p[u].x);
            float dy = __fsub_rn(qy, p[u].y);
            float dz = __fsub_rn(qz, p[u].z);
            d[u] = __fadd_rn(__fadd_rn(__fmul_rn(dx, dx), __fmul_rn(dy, dy)),
                             __fmul_rn(dz, dz));
        }
        bool p0 = d[0] <= worst_d, p1 = d[1] <= worst_d;
        bool p2 = d[2] <= worst_d, p3 = d[3] <= worst_d;
        if (__any_sync(0xffffffffu, p0 | p1 | p2 | p3)) {
            #pragma unroll
            for (int u = 0; u < 4; u++) {
                bool pu = (u == 0) ? p0 : (u == 1) ? p1 : (u == 2) ? p2 : p3;
                unsigned mask = __ballot_sync(0xffffffffu, pu);
                while (mask) {                       // warp-uniform loop
                    int src = __ffs(mask) - 1; mask &= mask - 1;
                    float dc = __shfl_sync(0xffffffffu, d[u], src);
                    int   ic = src + u * 32 + (i - lane);
                    if (dc < worst_d || (dc == worst_d && ic < worst_i)) {   // exact re-check
                        bool meq = (lane < 16) && (st_d == worst_d) && (st_i == worst_i);
                        unsigned bl = __ballot_sync(0xffffffffu, meq);
                        int wl = __ffs(bl) - 1;
                        if (lane == wl) { st_d = dc; st_i = ic; }
                        unsigned db = (lane < 16) ? __float_as_uint(st_d) : 0u;
                        unsigned wd = __reduce_max_sync(0xffffffffu, db);
                        unsigned ci = (db == wd && lane < 16) ? (unsigned)st_i : 0u;
                        unsigned wi = __reduce_max_sync(0xffffffffu, ci);
                        worst_d = __uint_as_float(wd);
                        worst_i = (int)wi;
                    }
                }
            }
        }
    }
    // emit sorted ascending (dist, then idx): 16 rounds of min-extraction
    bool act = (lane < 16);
    #pragma unroll 1
    for (int r = 0; r < 16; r++) {
        unsigned db = act ? __float_as_uint(st_d) : 0xFFFFFFFFu;
        unsigned md = __reduce_min_sync(0xffffffffu, db);
        unsigned ib = (act && db == md) ? (unsigned)st_i : 0xFFFFFFFFu;
        unsigned mi = __reduce_min_sync(0xffffffffu, ib);
        if (act && db == md && (unsigned)st_i == mi) {
            g_knn[gid * 16 + r] = st_i;
            act = false;
        }
    }
}

// ---------------- gather + WeightNet MLP + einsum agg: 1 block per point ----------------
__global__ void __launch_bounds__(128) agg_kernel(
    const float* __restrict__ w1, const float* __restrict__ b1,
    const float* __restrict__ w2, const float* __restrict__ b2,
    const float* __restrict__ w3, const float* __restrict__ b3)
{
    __shared__ float feat[KNB][CINC + 1];   // pad to 68
    __shared__ float wts[KNB][WNC];
    __shared__ int   nn[KNB];
    __shared__ float q[3];

    int t = threadIdx.x;
    int pid = blockIdx.x;
    int b = pid >> 10;

    if (t < KNB) nn[t] = g_knn[pid * KNB + t];
    if (t < 3)   q[t]  = g_newxyz[pid * 3 + t];
    __syncthreads();

    if (t < KNB) {
        float4 pp = g_xyzT4[b * NN + nn[t]];
        float gx = pp.x - q[0], gy = pp.y - q[1], gz = pp.z - q[2];
        feat[t][0] = gx; feat[t][1] = gy; feat[t][2] = gz;
        float h1[8], h2[8];
        #pragma unroll
        for (int j = 0; j < 8; j++) {
            float a = b1[j];
            a = fmaf(gx, w1[j], a);
            a = fmaf(gy, w1[8 + j], a);
            a = fmaf(gz, w1[16 + j], a);
            h1[j] = fmaxf(a, 0.f);
        }
        #pragma unroll
        for (int j = 0; j < 8; j++) {
            float a = b2[j];
            #pragma unroll
            for (int i = 0; i < 8; i++) a = fmaf(h1[i], w2[i * 8 + j], a);
            h2[j] = fmaxf(a, 0.f);
        }
        #pragma unroll
        for (int j = 0; j < 16; j++) {
            float a = b3[j];
            #pragma unroll
            for (int i = 0; i < 8; i++) a = fmaf(h2[i], w3[i * 16 + j], a);
            wts[t][j] = fmaxf(a, 0.f);
        }
    }
    for (int idx = t; idx < KNB * DD; idx += 128) {
        int k = idx >> 6, d = idx & 63;
        feat[k][3 + d] = g_ptsT[((size_t)b * NN + nn[k]) * DD + d];
    }
    __syncthreads();

    for (int j = t; j < AGGW; j += 128) {
        int c = j >> 4, w = j & 15;
        float a = 0.f;
        #pragma unroll
        for (int k = 0; k < KNB; k++) a = fmaf(feat[k][c], wts[k][w], a);
        g_agg[(size_t)pid * AGGW + j] = a;
    }
}

// ---------------- final linear: GEMM [8192 x 1072] * [1072 x 128] + bias + leaky ----------------
__global__ void __launch_bounds__(256) gemm_kernel(
    const float* __restrict__ lin_w, const float* __restrict__ lin_b,
    float* __restrict__ dout)
{
    __shared__ float As[64][16];
    __shared__ float Bs[16][128];
    int t = threadIdx.x;
    int row0 = blockIdx.x * 64;
    int cg = t & 31, rg = t >> 5;

    float acc[8][4];
    #pragma unroll
    for (int i = 0; i < 8; i++)
        #pragma unroll
        for (int j = 0; j < 4; j++) acc[i][j] = 0.f;

    for (int k0 = 0; k0 < AGGW; k0 += 16) {
        __syncthreads();
        {
            int r = t >> 2, kk = (t & 3) << 2;
            float4 v = *(const float4*)&g_agg[(size_t)(row0 + r) * AGGW + k0 + kk];
            *(float4*)&As[r][kk] = v;
        }
        {
            int kk = t >> 5, c = (t & 31) << 2;
            *(float4*)&Bs[kk][c]     = *(const float4*)&lin_w[(size_t)(k0 + kk) * 128 + c];
            *(float4*)&Bs[kk + 8][c] = *(const float4*)&lin_w[(size_t)(k0 + kk + 8) * 128 + c];
        }
        __syncthreads();
        #pragma unroll
        for (int kk = 0; kk < 16; kk++) {
            float4 bv = *(float4*)&Bs[kk][cg << 2];
            #pragma unroll
            for (int ri = 0; ri < 8; ri++) {
                float av = As[rg * 8 + ri][kk];
                acc[ri][0] = fmaf(av, bv.x, acc[ri][0]);
                acc[ri][1] = fmaf(av, bv.y, acc[ri][1]);
                acc[ri][2] = fmaf(av, bv.z, acc[ri][2]);
                acc[ri][3] = fmaf(av, bv.w, acc[ri][3]);
            }
        }
    }
    float bias[4];
    #pragma unroll
    for (int ci = 0; ci < 4; ci++) bias[ci] = lin_b[(cg << 2) + ci];
    #pragma unroll
    for (int ri = 0; ri < 8; ri++) {
        int p = row0 + rg * 8 + ri;
        int b = p >> 10, s = p & 1023;
        #pragma unroll
        for (int ci = 0; ci < 4; ci++) {
            int c = (cg << 2) + ci;
            float v = acc[ri][ci] + bias[ci];
            v = (v > 0.f) ? v : 0.1f * v;
            dout[OFF_OUT + ((size_t)b * OUTC + c) * SS + s] = v;
        }
    }
}

// ---------------- launch ----------------
extern "C" void kernel_launch(void* const* d_in, const int* in_sizes, int n_in,
                              void* d_out, int out_size) {
    const float* xyz = (const float*)d_in[0];
    const float* pts = (const float*)d_in[1];
    const float* w1  = (const float*)d_in[2];
    const float* b1  = (const float*)d_in[3];
    const float* w2  = (const float*)d_in[4];
    const float* b2  = (const float*)d_in[5];
    const float* w3  = (const float*)d_in[6];
    const float* b3  = (const float*)d_in[7];
    const float* lw  = (const float*)d_in[8];
    const float* lb  = (const float*)d_in[9];
    float* out = (float*)d_out;

    xyzT_kernel<<<BB * NN / 256, 256>>>(xyz);
    ptsT_kernel<<<dim3(NN / 32, DD / 32, BB), dim3(32, 8)>>>(pts);
    fps_kernel<<<BB, 1024>>>(out);
    knn_kernel<<<BB * SS / 16, 512>>>();
    agg_kernel<<<BB * SS, 128>>>(w1, b1, w2, b2, w3, b3);
    gemm_kernel<<<BB * SS / 64, 256>>>(lw, lb, out);
}

// round 17
// speedup vs baseline: 1.3969x; 1.0889x over previous
#include <cuda_runtime.h>
#include <cfloat>

#define BB   8
#define NN   8192
#define DD   64
#define SS   1024
#define KNB  16          // NSAMPLE
#define WNC  16          // weightnet out channels
#define OUTC 128
#define CINC 67          // 3 + D
#define AGGW (CINC*WNC)  // 1072

#define OFF_OUT (BB*3*SS)                 // 24576
#define OFF_IDX (BB*3*SS + BB*OUTC*SS)    // 1073152

// ---------------- scratch: ONE static device buffer, no allocation ----------------
#define SC_XYZT   0
#define SC_PTST   (SC_XYZT + BB*NN*4)
#define SC_NEWXYZ (SC_PTST + BB*NN*DD)
#define SC_KNN    (SC_NEWXYZ + BB*SS*3)
#define SC_AGG    (SC_KNN + BB*SS*KNB)
#define SC_TOTAL  (SC_AGG + (size_t)BB*SS*AGGW)

__device__ __align__(16) float g_scratch[SC_TOTAL];

#define g_xyzT4  ((float4*)(g_scratch + SC_XYZT))
#define g_ptsT   (g_scratch + SC_PTST)
#define g_newxyz (g_scratch + SC_NEWXYZ)
#define g_knn    ((int*)(g_scratch + SC_KNN))
#define g_agg    (g_scratch + SC_AGG)

// ---------------- packed f32x2 helpers (Blackwell, exact per-element rn) ----------------
__device__ __forceinline__ unsigned long long pk2(float lo, float hi) {
    unsigned long long r;
    asm("mov.b64 %0, {%1, %2};" : "=l"(r) : "f"(lo), "f"(hi));
    return r;
}
__device__ __forceinline__ void upk2(unsigned long long v, float& lo, float& hi) {
    asm("mov.b64 {%0, %1}, %2;" : "=f"(lo), "=f"(hi) : "l"(v));
}
__device__ __forceinline__ unsigned long long addx2(unsigned long long a, unsigned long long b) {
    unsigned long long r;
    asm("add.rn.f32x2 %0, %1, %2;" : "=l"(r) : "l"(a), "l"(b));
    return r;
}
__device__ __forceinline__ unsigned long long mulx2(unsigned long long a, unsigned long long b) {
    unsigned long long r;
    asm("mul.rn.f32x2 %0, %1, %2;" : "=l"(r) : "l"(a), "l"(b));
    return r;
}

// ---------------- layout transforms ----------------
__global__ void xyzT_kernel(const float* __restrict__ xyz) {
    int i = blockIdx.x * 256 + threadIdx.x;     // 0 .. BB*NN-1
    int b = i >> 13, n = i & (NN - 1);
    const float* X = xyz + (size_t)b * 3 * NN;
    g_xyzT4[i] = make_float4(X[n], X[NN + n], X[2 * NN + n], 0.f);
}

__global__ void ptsT_kernel(const float* __restrict__ pts) {
    __shared__ float tile[32][33];
    int b = blockIdx.z;
    int n0 = blockIdx.x * 32, d0 = blockIdx.y * 32;
    int tx = threadIdx.x, ty = threadIdx.y;
    #pragma unroll
    for (int i = 0; i < 32; i += 8)
        tile[ty + i][tx] = pts[(size_t)b * DD * NN + (size_t)(d0 + ty + i) * NN + n0 + tx];
    __syncthreads();
    #pragma unroll
    for (int i = 0; i < 32; i += 8)
        g_ptsT[((size_t)b * NN + n0 + ty + i) * DD + d0 + tx] = tile[tx][ty + i];
}

// ---------------- FPS: 1 block per batch, 512 threads, 16 pts/thread ----------------
// Fewer, fatter warps: the per-warp reduction tail (~27 instr) amortizes over 16
// points instead of 8. Hot loop: packed f32x2 dist (exact rn) + FMNMX min/max.
// Argmax index resolved post-hoc on matching lanes (exact first-occurrence rule).
__global__ void __launch_bounds__(512, 1) fps_kernel(float* __restrict__ dout) {
    int b = blockIdx.x;
    int t = threadIdx.x;
    int lane = t & 31, warp = t >> 5;     // 16 warps

    // element e (0..15) is point t + (e<<9); pairs (2j, 2j+1) packed
    unsigned long long ppx[8], ppy[8], ppz[8];
    float dist[16];
    #pragma unroll
    for (int j = 0; j < 8; j++) {
        float4 p0 = g_xyzT4[b * NN + t + ((2 * j) << 9)];
        float4 p1 = g_xyzT4[b * NN + t + ((2 * j + 1) << 9)];
        ppx[j] = pk2(p0.x, p1.x);
        ppy[j] = pk2(p0.y, p1.y);
        ppz[j] = pk2(p0.z, p1.z);
        dist[2 * j] = 1e10f; dist[2 * j + 1] = 1e10f;
    }

    __shared__ float    s_bd[2][16];
    __shared__ unsigned s_bi[2][16];

    int far = 0;
    for (int s = 0; s < SS; s++) {
        float4 c = g_xyzT4[b * NN + far];   // broadcast load (L1-resident)
        if (t == 0) {
            dout[b * 3 * SS + s]          = c.x;
            dout[b * 3 * SS + SS + s]     = c.y;
            dout[b * 3 * SS + 2 * SS + s] = c.z;
            dout[OFF_IDX + b * SS + s]    = (float)far;
            int gs = (b * SS + s) * 3;
            g_newxyz[gs] = c.x; g_newxyz[gs + 1] = c.y; g_newxyz[gs + 2] = c.z;
        }
        // negated centroid, packed (exact: rn-add of -c == rn-sub of c)
        unsigned long long ncx = pk2(-c.x, -c.x);
        unsigned long long ncy = pk2(-c.y, -c.y);
        unsigned long long ncz = pk2(-c.z, -c.z);

        #pragma unroll
        for (int j = 0; j < 8; j++) {
            unsigned long long dx = addx2(ppx[j], ncx);
            unsigned long long dy = addx2(ppy[j], ncy);
            unsigned long long dz = addx2(ppz[j], ncz);
            unsigned long long xx = mulx2(dx, dx);
            unsigned long long yy = mulx2(dy, dy);
            unsigned long long s1 = addx2(xx, yy);
            unsigned long long zz = mulx2(dz, dz);
            unsigned long long dd = addx2(s1, zz);
            float d0, d1;
            upk2(dd, d0, d1);
            dist[2 * j]     = fminf(dist[2 * j], d0);
            dist[2 * j + 1] = fminf(dist[2 * j + 1], d1);
        }
        // index-free per-thread max (FMNMX tree over 16)
        float m;
        {
            float a0 = fmaxf(dist[0], dist[1]);
            float a1 = fmaxf(dist[2], dist[3]);
            float a2 = fmaxf(dist[4], dist[5]);
            float a3 = fmaxf(dist[6], dist[7]);
            float a4 = fmaxf(dist[8], dist[9]);
            float a5 = fmaxf(dist[10], dist[11]);
            float a6 = fmaxf(dist[12], dist[13]);
            float a7 = fmaxf(dist[14], dist[15]);
            float b0 = fmaxf(a0, a1), b1 = fmaxf(a2, a3);
            float b2 = fmaxf(a4, a5), b3 = fmaxf(a6, a7);
            m = fmaxf(fmaxf(b0, b1), fmaxf(b2, b3));
        }
        // warp max via REDUX (dist >= 0: float bits order as u32)
        unsigned mb  = __float_as_uint(m);
        unsigned wmb = __reduce_max_sync(0xffffffffu, mb);
        // index resolution on matching lanes; ascending e => ascending idx,
        // min over matches == first occurrence (exact argmax tie rule)
        unsigned cand = 0xffffffffu;
        if (mb == wmb) {
            #pragma unroll
            for (int e = 15; e >= 0; e--)
                if (dist[e] == m) cand = (unsigned)(t + (e << 9));
        }
        unsigned wbi = __reduce_min_sync(0xffffffffu, cand);
        if (lane == 0) { s_bd[s & 1][warp] = __uint_as_float(wmb); s_bi[s & 1][warp] = wbi; }
        __syncthreads();
        // level-2: every warp reduces the 16 per-warp results (single barrier/iter);
        // lanes 16..31 carry sentinels (vb=0 can't exceed a real max; even on a
        // gmax==0 degenerate tie, real candidates are in the min set).
        unsigned vb = (lane < 16) ? __float_as_uint(s_bd[s & 1][lane]) : 0u;
        unsigned vi = (lane < 16) ? s_bi[s & 1][lane] : 0xffffffffu;
        unsigned gmax = __reduce_max_sync(0xffffffffu, vb);
        unsigned gc   = (vb == gmax) ? vi : 0xffffffffu;
        far = (int)__reduce_min_sync(0xffffffffu, gc);
    }
}

// ---------------- KNN: 1 warp per sampled point, warp-collective exact top-16 ----------------
// 4 candidates per lane-iteration (MLP 4). Top-16 set is order-invariant under the
// lexicographic (dist, idx) accept/evict rules, so batch processing order is safe.
// Gate d <= worst_d only over-triggers; the uniform re-check inside is exact.
// 256-thread blocks (grid 1024) for finer cross-SM load balancing.
__global__ void __launch_bounds__(256) knn_kernel() {
    int w = threadIdx.x >> 5, lane = threadIdx.x & 31;
    int gid = blockIdx.x * 8 + w;           // 0..8191
    int b = gid >> 10;

    float qx = g_newxyz[gid * 3], qy = g_newxyz[gid * 3 + 1], qz = g_newxyz[gid * 3 + 2];
    const float4* X4 = g_xyzT4 + b * NN;

    float st_d = FLT_MAX;            // stored entry (meaningful in lanes 0..15)
    int   st_i = 0x7FFFFFFF;
    float worst_d = FLT_MAX;         // warp-uniform: max dist among stored, tie max idx
    int   worst_i = 0x7FFFFFFF;

    for (int i = lane; i < NN; i += 128) {
        float4 p[4];
        #pragma unroll
        for (int u = 0; u < 4; u++) p[u] = X4[i + u * 32];
        float d[4];
        #pragma unroll
        for (int u = 0; u < 4; u++) {
            float dx = __fsub_rn(qx, p[u].x);
            float dy = __fsub_rn(qy, p[u].y);
            float dz = __fsub_rn(qz, p[u].z);
            d[u] = __fadd_rn(__fadd_rn(__fmul_rn(dx, dx), __fmul_rn(dy, dy)),
                             __fmul_rn(dz, dz));
        }
        bool p0 = d[0] <= worst_d, p1 = d[1] <= worst_d;
        bool p2 = d[2] <= worst_d, p3 = d[3] <= worst_d;
        if (__any_sync(0xffffffffu, p0 | p1 | p2 | p3)) {
            #pragma unroll
            for (int u = 0; u < 4; u++) {
                bool pu = (u == 0) ? p0 : (u == 1) ? p1 : (u == 2) ? p2 : p3;
                unsigned mask = __ballot_sync(0xffffffffu, pu);
                while (mask) {                       // warp-uniform loop
                    int src = __ffs(mask) - 1; mask &= mask - 1;
                    float dc = __shfl_sync(0xffffffffu, d[u], src);
                    int   ic = src + u * 32 + (i - lane);
                    if (dc < worst_d || (dc == worst_d && ic < worst_i)) {   // exact re-check
                        bool meq = (lane < 16) && (st_d == worst_d) && (st_i == worst_i);
                        unsigned bl = __ballot_sync(0xffffffffu, meq);
                        int wl = __ffs(bl) - 1;
                        if (lane == wl) { st_d = dc; st_i = ic; }
                        unsigned db = (lane < 16) ? __float_as_uint(st_d) : 0u;
                        unsigned wd = __reduce_max_sync(0xffffffffu, db);
                        unsigned ci = (db == wd && lane < 16) ? (unsigned)st_i : 0u;
                        unsigned wi = __reduce_max_sync(0xffffffffu, ci);
                        worst_d = __uint_as_float(wd);
                        worst_i = (int)wi;
                    }
                }
            }
        }
    }
    // emit sorted ascending (dist, then idx): 16 rounds of min-extraction
    bool act = (lane < 16);
    #pragma unroll 1
    for (int r = 0; r < 16; r++) {
        unsigned db = act ? __float_as_uint(st_d) : 0xFFFFFFFFu;
        unsigned md = __reduce_min_sync(0xffffffffu, db);
        unsigned ib = (act && db == md) ? (unsigned)st_i : 0xFFFFFFFFu;
        unsigned mi = __reduce_min_sync(0xffffffffu, ib);
        if (act && db == md && (unsigned)st_i == mi) {
            g_knn[gid * 16 + r] = st_i;
            act = false;
        }
    }
}

// ---------------- gather + WeightNet MLP + einsum agg: 1 block per point ----------------
__global__ void __launch_bounds__(128) agg_kernel(
    const float* __restrict__ w1, const float* __restrict__ b1,
    const float* __restrict__ w2, const float* __restrict__ b2,
    const float* __restrict__ w3, const float* __restrict__ b3)
{
    __shared__ float feat[KNB][CINC + 1];   // pad to 68
    __shared__ float wts[KNB][WNC];
    __shared__ int   nn[KNB];
    __shared__ float q[3];

    int t = threadIdx.x;
    int pid = blockIdx.x;
    int b = pid >> 10;

    if (t < KNB) nn[t] = g_knn[pid * KNB + t];
    if (t < 3)   q[t]  = g_newxyz[pid * 3 + t];
    __syncthreads();

    if (t < KNB) {
        float4 pp = g_xyzT4[b * NN + nn[t]];
        float gx = pp.x - q[0], gy = pp.y - q[1], gz = pp.z - q[2];
        feat[t][0] = gx; feat[t][1] = gy; feat[t][2] = gz;
        float h1[8], h2[8];
        #pragma unroll
        for (int j = 0; j < 8; j++) {
            float a = b1[j];
            a = fmaf(gx, w1[j], a);
            a = fmaf(gy, w1[8 + j], a);
            a = fmaf(gz, w1[16 + j], a);
            h1[j] = fmaxf(a, 0.f);
        }
        #pragma unroll
        for (int j = 0; j < 8; j++) {
            float a = b2[j];
            #pragma unroll
            for (int i = 0; i < 8; i++) a = fmaf(h1[i], w2[i * 8 + j], a);
            h2[j] = fmaxf(a, 0.f);
        }
        #pragma unroll
        for (int j = 0; j < 16; j++) {
            float a = b3[j];
            #pragma unroll
            for (int i = 0; i < 8; i++) a = fmaf(h2[i], w3[i * 16 + j], a);
            wts[t][j] = fmaxf(a, 0.f);
        }
    }
    for (int idx = t; idx < KNB * DD; idx += 128) {
        int k = idx >> 6, d = idx & 63;
        feat[k][3 + d] = g_ptsT[((size_t)b * NN + nn[k]) * DD + d];
    }
    __syncthreads();

    for (int j = t; j < AGGW; j += 128) {
        int c = j >> 4, w = j & 15;
        float a = 0.f;
        #pragma unroll
        for (int k = 0; k < KNB; k++) a = fmaf(feat[k][c], wts[k][w], a);
        g_agg[(size_t)pid * AGGW + j] = a;
    }
}

// ---------------- final linear: GEMM [8192 x 1072] * [1072 x 128] + bias + leaky ----------------
__global__ void __launch_bounds__(256) gemm_kernel(
    const float* __restrict__ lin_w, const float* __restrict__ lin_b,
    float* __restrict__ dout)
{
    __shared__ float As[64][16];
    __shared__ float Bs[16][128];
    int t = threadIdx.x;
    int row0 = blockIdx.x * 64;
    int cg = t & 31, rg = t >> 5;

    float acc[8][4];
    #pragma unroll
    for (int i = 0; i < 8; i++)
        #pragma unroll
        for (int j = 0; j < 4; j++) acc[i][j] = 0.f;

    for (int k0 = 0; k0 < AGGW; k0 += 16) {
        __syncthreads();
        {
            int r = t >> 2, kk = (t & 3) << 2;
            float4 v = *(const float4*)&g_agg[(size_t)(row0 + r) * AGGW + k0 + kk];
            *(float4*)&As[r][kk] = v;
        }
        {
            int kk = t >> 5, c = (t & 31) << 2;
            *(float4*)&Bs[kk][c]     = *(const float4*)&lin_w[(size_t)(k0 + kk) * 128 + c];
            *(float4*)&Bs[kk + 8][c] = *(const float4*)&lin_w[(size_t)(k0 + kk + 8) * 128 + c];
        }
        __syncthreads();
        #pragma unroll
        for (int kk = 0; kk < 16; kk++) {
            float4 bv = *(float4*)&Bs[kk][cg << 2];
            #pragma unroll
            for (int ri = 0; ri < 8; ri++) {
                float av = As[rg * 8 + ri][kk];
                acc[ri][0] = fmaf(av, bv.x, acc[ri][0]);
                acc[ri][1] = fmaf(av, bv.y, acc[ri][1]);
                acc[ri][2] = fmaf(av, bv.z, acc[ri][2]);
                acc[ri][3] = fmaf(av, bv.w, acc[ri][3]);
            }
        }
    }
    float bias[4];
    #pragma unroll
    for (int ci = 0; ci < 4; ci++) bias[ci] = lin_b[(cg << 2) + ci];
    #pragma unroll
    for (int ri = 0; ri < 8; ri++) {
        int p = row0 + rg * 8 + ri;
        int b = p >> 10, s = p & 1023;
        #pragma unroll
        for (int ci = 0; ci < 4; ci++) {
            int c = (cg << 2) + ci;
            float v = acc[ri][ci] + bias[ci];
            v = (v > 0.f) ? v : 0.1f * v;
            dout[OFF_OUT + ((size_t)b * OUTC + c) * SS + s] = v;
        }
    }
}

// ---------------- launch ----------------
extern "C" void kernel_launch(void* const* d_in, const int* in_sizes, int n_in,
                              void* d_out, int out_size) {
    const float* xyz = (const float*)d_in[0];
    const float* pts = (const float*)d_in[1];
    const float* w1  = (const float*)d_in[2];
    const float* b1  = (const float*)d_in[3];
    const float* w2  = (const float*)d_in[4];
    const float* b2  = (const float*)d_in[5];
    const float* w3  = (const float*)d_in[6];
    const float* b3  = (const float*)d_in[7];
    const float* lw  = (const float*)d_in[8];
    const float* lb  = (const float*)d_in[9];
    float* out = (float*)d_out;

    xyzT_kernel<<<BB * NN / 256, 256>>>(xyz);
    ptsT_kernel<<<dim3(NN / 32, DD / 32, BB), dim3(32, 8)>>>(pts);
    fps_kernel<<<BB, 512>>>(out);
    knn_kernel<<<BB * SS / 8, 256>>>();
    agg_kernel<<<BB * SS, 128>>>(w1, b1, w2, b2, w3, b3);
    gemm_kernel<<<BB * SS / 64, 256>>>(lw, lb, out);
}